// round 16
// baseline (speedup 1.0000x reference)
#include <cuda_runtime.h>
#include <math.h>

#define N_USERS   100000
#define N_ITEMS   50000
#define N_NODES   150000
#define DIM       128
#define KINT      8
#define E_G       1500000
#define NL        65536
#define EL        262144
#define BATCH     1024

#define OUT_PRED  0
#define OUT_GU    1024
#define OUT_HSUB  (1024 + 131072)
#define OUT_PU    (1024 + 2*131072)
#define OUT_PV    (1024 + 2*131072 + 8192)
#define OUT_TOTAL (1024 + 2*131072 + 2*8192)

#define XS 132            // padded smem row stride (floats)
#define GEMM_SMEM (2 * 128 * XS * 4)

#define SCAN_B 1024
#define NSEG_G ((N_NODES + SCAN_B - 1) / SCAN_B)   // 147
#define NSEG_L (NL / SCAN_B)                        // 64

// ---------------- scratch (device globals; zero-initialized) ------------------
__device__ float g_Y[N_NODES * DIM];
__device__ float g_aggr[N_NODES * DIM];
__device__ float g_xw[NL * DIM];
__device__ float g_lout[NL * DIM];
__device__ float g_PG[128 * DIM];    // only top 128 rows needed (xw_gemm)
__device__ float g_D4[4 * DIM];
__device__ float g_dinv[NL];
__device__ float g_gu[BATCH * DIM];
__device__ float g_gi[BATCH * DIM];
__device__ float g_ru[BATCH * DIM];
__device__ float g_rv[BATCH * DIM];
// CSR scratch: global edges (self-cleaned by gather_aggr each call)
__device__ int   g_cnt[N_NODES];
__device__ int   g_cur[N_NODES];
__device__ int   g_bsumG[NSEG_G];
__device__ int   g_epack[E_G];       // src | (attr << 24)
// CSR scratch: local edges (self-cleaned by lgather_kernel each call)
__device__ int   g_lcnt[NL];
__device__ int   g_lcur[NL];
__device__ int   g_bsumL[NSEG_L];
__device__ int   g_lpack[EL];        // src

__device__ __forceinline__ unsigned f2tf32(float f) {
    unsigned r;
    asm("cvt.rna.tf32.f32 %0, %1;" : "=r"(r) : "f"(f));
    return r;
}
__device__ __forceinline__ void mma_tf32(float c[4], unsigned a0, unsigned a1,
                                         unsigned a2, unsigned a3,
                                         unsigned b0, unsigned b1) {
    asm volatile("mma.sync.aligned.m16n8k8.row.col.f32.tf32.tf32.f32 "
                 "{%0,%1,%2,%3}, {%4,%5,%6,%7}, {%8,%9}, {%0,%1,%2,%3};"
                 : "+f"(c[0]), "+f"(c[1]), "+f"(c[2]), "+f"(c[3])
                 : "r"(a0), "r"(a1), "r"(a2), "r"(a3), "r"(b0), "r"(b1));
}
__device__ __forceinline__ void stcs_i(int* p, int v) {
    asm volatile("st.global.cs.s32 [%0], %1;" :: "l"(p), "r"(v) : "memory");
}
__device__ __forceinline__ int ldcs_i(const int* p) {
    int v;
    asm volatile("ld.global.cs.s32 %0, [%1];" : "=r"(v) : "l"(p));
    return v;
}

// ---------------- merged histogram: global + local edges ----------------------
// cnt arrays are guaranteed zero on entry (static init / self-clean of prior call)
__global__ void hist_both(const int* __restrict__ gdst, const int* __restrict__ ldst) {
    int e = blockIdx.x * blockDim.x + threadIdx.x;
    if (e < E_G) {
        atomicAdd(&g_cnt[gdst[e]], 1);
    } else if (e < E_G + EL) {
        atomicAdd(&g_lcnt[ldst[e - E_G]], 1);
    }
}

// ---------------- merged scan pass A (per-segment sums) -----------------------
__global__ void __launch_bounds__(SCAN_B) scan_a_both() {
    __shared__ int sh[SCAN_B];
    int blk = blockIdx.x;
    const int* cnt; int n; int* bsum; int seg;
    if (blk < NSEG_G) { cnt = g_cnt;  n = N_NODES; bsum = g_bsumG; seg = blk; }
    else              { cnt = g_lcnt; n = NL;      bsum = g_bsumL; seg = blk - NSEG_G; }
    int tid = threadIdx.x;
    int i = seg * SCAN_B + tid;
    sh[tid] = (i < n) ? cnt[i] : 0;
    __syncthreads();
    for (int s = SCAN_B / 2; s > 0; s >>= 1) {
        if (tid < s) sh[tid] += sh[tid + s];
        __syncthreads();
    }
    if (tid == 0) bsum[seg] = sh[0];
}

// ---------------- scan pass C (base from segment sums + in-block prefix) ------
__global__ void __launch_bounds__(SCAN_B) scan_c_both() {
    __shared__ int sh[SCAN_B];
    __shared__ int baseSh;
    int blk = blockIdx.x;
    int tid = threadIdx.x;
    bool isLocal = (blk >= NSEG_G);
    int* cnt; int* cur; int n; const int* bsum; int seg;
    if (!isLocal) { cnt = g_cnt;  cur = g_cur;  n = N_NODES; bsum = g_bsumG; seg = blk; }
    else          { cnt = g_lcnt; cur = g_lcur; n = NL;      bsum = g_bsumL; seg = blk - NSEG_G; }

    // base = sum of prior segments' totals
    sh[tid] = (tid < seg) ? bsum[tid] : 0;     // seg <= 147 < SCAN_B
    __syncthreads();
    for (int s = SCAN_B / 2; s > 0; s >>= 1) {
        if (tid < s) sh[tid] += sh[tid + s];
        __syncthreads();
    }
    if (tid == 0) baseSh = sh[0];
    __syncthreads();
    int base = baseSh;
    __syncthreads();

    // inclusive prefix over this segment's counts
    int i = seg * SCAN_B + tid;
    int v = (i < n) ? cnt[i] : 0;
    sh[tid] = v;
    __syncthreads();
    for (int ofs = 1; ofs < SCAN_B; ofs <<= 1) {
        int t = (tid >= ofs) ? sh[tid - ofs] : 0;
        __syncthreads();
        sh[tid] += t;
        __syncthreads();
    }
    if (i < n) {
        int excl = sh[tid] - v + base;
        cnt[i] = excl;
        cur[i] = excl;
        if (isLocal) g_dinv[i] = rsqrtf((float)(v + 1));  // deg = in-edges + self loop
    }
}

// ---------------- merged fill: global + local (streaming stores) --------------
__global__ void fill_both(const int* __restrict__ gsrc, const int* __restrict__ gdst,
                          const int* __restrict__ attr,
                          const int* __restrict__ lsrc, const int* __restrict__ ldst) {
    int e = blockIdx.x * blockDim.x + threadIdx.x;
    if (e < E_G) {
        int pos = atomicAdd(&g_cur[gdst[e]], 1);
        stcs_i(&g_epack[pos], gsrc[e] | (attr[e] << 24));
    } else if (e < E_G + EL) {
        int le = e - E_G;
        int pos = atomicAdd(&g_lcur[ldst[le]], 1);
        stcs_i(&g_lpack[pos], lsrc[le]);
    }
}

// ---------------- Y = all_emb @ W + b  (tf32 tensor-core GEMM) ---------------
__global__ void __launch_bounds__(256) y_gemm_tc(const float* __restrict__ ue,
                                                 const float* __restrict__ ie,
                                                 const float* __restrict__ W,
                                                 const float* __restrict__ bias) {
    extern __shared__ float sm[];
    float* Wsm = sm;
    float* Xsm = sm + 128 * XS;
    int tid = threadIdx.x;
    int r0 = blockIdx.x * 128;

#pragma unroll
    for (int t = 0; t < 16; t++) {
        int i = tid + t * 256;
        int row = i >> 5, q = i & 31;
        float4 v = ((const float4*)W)[row * 32 + q];
        *(float4*)&Wsm[row * XS + q * 4] = v;
    }
#pragma unroll
    for (int t = 0; t < 16; t++) {
        int i = tid + t * 256;
        int row = i >> 5, q = i & 31;
        int r = r0 + row;
        float4 v = make_float4(0.f, 0.f, 0.f, 0.f);
        if (r < N_NODES) {
            const float* p = (r < N_USERS) ? (ue + (size_t)r * DIM)
                                           : (ie + (size_t)(r - N_USERS) * DIM);
            v = ((const float4*)p)[q];
        }
        *(float4*)&Xsm[row * XS + q * 4] = v;
    }
    __syncthreads();

    int warp = tid >> 5, lane = tid & 31;
    int gid = lane >> 2, tig = lane & 3;
    int wr = warp * 16;

    float acc[16][4];
#pragma unroll
    for (int n = 0; n < 16; n++)
#pragma unroll
        for (int m = 0; m < 4; m++) acc[n][m] = 0.f;

#pragma unroll
    for (int k = 0; k < 128; k += 8) {
        unsigned a0 = f2tf32(Xsm[(wr + gid) * XS + k + tig]);
        unsigned a1 = f2tf32(Xsm[(wr + gid + 8) * XS + k + tig]);
        unsigned a2 = f2tf32(Xsm[(wr + gid) * XS + k + tig + 4]);
        unsigned a3 = f2tf32(Xsm[(wr + gid + 8) * XS + k + tig + 4]);
#pragma unroll
        for (int n = 0; n < 16; n++) {
            unsigned b0 = f2tf32(Wsm[(k + tig) * XS + n * 8 + gid]);
            unsigned b1 = f2tf32(Wsm[(k + tig + 4) * XS + n * 8 + gid]);
            mma_tf32(acc[n], a0, a1, a2, a3, b0, b1);
        }
    }

    int row0 = r0 + wr + gid;
    int row1 = row0 + 8;
#pragma unroll
    for (int n = 0; n < 16; n++) {
        int c0 = n * 8 + tig * 2;
        float bx = bias[c0], by = bias[c0 + 1];
        if (row0 < N_NODES) {
            float2 o = make_float2(acc[n][0] + bx, acc[n][1] + by);
            *(float2*)&g_Y[(size_t)row0 * DIM + c0] = o;
        }
        if (row1 < N_NODES) {
            float2 o = make_float2(acc[n][2] + bx, acc[n][3] + by);
            *(float2*)&g_Y[(size_t)row1 * DIM + c0] = o;
        }
    }
}

// ---------------- aggr[d] = sum over in-edges of sign * Y[src]  (gather) -----
// self-cleans g_cnt/g_cur for the next call.
__global__ void __launch_bounds__(256) gather_aggr(const float* __restrict__ sign_emb) {
    int warp = (blockIdx.x * blockDim.x + threadIdx.x) >> 5;
    int lane = threadIdx.x & 31;
    if (warp >= N_NODES) return;
    float sA = __ldg(sign_emb);
    float sB = __ldg(sign_emb + 1);
    int p   = g_cnt[warp];
    int end = g_cur[warp];
    if (lane == 0) { g_cnt[warp] = 0; g_cur[warp] = 0; }
    float4 acc = make_float4(0.f, 0.f, 0.f, 0.f);
    for (; p + 1 < end; p += 2) {
        int pk0 = ldcs_i(&g_epack[p]);
        int pk1 = ldcs_i(&g_epack[p + 1]);
        int s0 = pk0 & 0xFFFFFF;
        int s1 = pk1 & 0xFFFFFF;
        float4 v0 = ((const float4*)g_Y)[(size_t)s0 * 32 + lane];
        float4 v1 = ((const float4*)g_Y)[(size_t)s1 * 32 + lane];
        float sg0 = (pk0 >> 24) ? sB : sA;
        float sg1 = (pk1 >> 24) ? sB : sA;
        acc.x += sg0 * v0.x + sg1 * v1.x;
        acc.y += sg0 * v0.y + sg1 * v1.y;
        acc.z += sg0 * v0.z + sg1 * v1.z;
        acc.w += sg0 * v0.w + sg1 * v1.w;
    }
    if (p < end) {
        int pk = ldcs_i(&g_epack[p]);
        int s = pk & 0xFFFFFF;
        float sg = (pk >> 24) ? sB : sA;
        float4 v = ((const float4*)g_Y)[(size_t)s * 32 + lane];
        acc.x += sg * v.x; acc.y += sg * v.y; acc.z += sg * v.z; acc.w += sg * v.w;
    }
    ((float4*)g_aggr)[(size_t)warp * 32 + lane] = acc;
}

// ---------------- intent heads (gugi folded in) -------------------------------
__global__ void __launch_bounds__(128) intent_kernel(const int* __restrict__ root_u,
                                                     const int* __restrict__ root_i,
                                                     const float* __restrict__ ue,
                                                     const float* __restrict__ ie,
                                                     const float* __restrict__ w1,
                                                     const float* __restrict__ b1,
                                                     const float* __restrict__ w2,
                                                     const float* __restrict__ b2,
                                                     const float* __restrict__ c_u,
                                                     const float* __restrict__ c_v,
                                                     float* __restrict__ out, int out_size) {
    __shared__ float xs[DIM];
    __shared__ float h1[DIM];
    __shared__ float lg[KINT];
    __shared__ float ps[KINT];
    int side = blockIdx.x >> 10;
    int b = blockIdx.x & 1023;
    int j = threadIdx.x;

    int node = side ? (root_i[b] + N_USERS) : root_u[b];
    const float* emb = (node < N_USERS) ? (ue + (size_t)node * DIM)
                                        : (ie + (size_t)(node - N_USERS) * DIM);
    float ev = emb[j];
    float av = g_aggr[(size_t)node * DIM + j];
    float r0 = ev + fmaxf(av, 0.f);
    xs[j] = r0;
    (side ? g_gi : g_gu)[b * DIM + j] = r0;
    if (!side && out_size >= OUT_TOTAL) out[OUT_GU + b * DIM + j] = r0;
    __syncthreads();

    float a = b1[j];
#pragma unroll 8
    for (int k = 0; k < DIM; k++) a += xs[k] * w1[k * DIM + j];
    h1[j] = tanhf(a);
    __syncthreads();
    if (j < KINT) {
        float l = b2[j];
        for (int k = 0; k < DIM; k++) l += h1[k] * w2[k * KINT + j];
        lg[j] = l;
    }
    __syncthreads();
    if (j == 0) {
        float m = lg[0];
        for (int t = 1; t < KINT; t++) m = fmaxf(m, lg[t]);
        float s = 0.f;
        for (int t = 0; t < KINT; t++) { ps[t] = expf(lg[t] - m); s += ps[t]; }
        float inv = 1.f / s;
        for (int t = 0; t < KINT; t++) ps[t] *= inv;
    }
    __syncthreads();
    const float* proto = side ? c_v : c_u;
    float r = 0.f;
#pragma unroll
    for (int t = 0; t < KINT; t++) r += ps[t] * proto[t * DIM + j];
    (side ? g_rv : g_ru)[b * DIM + j] = r;
    if (j < KINT && out_size >= OUT_TOTAL)
        out[(side ? OUT_PV : OUT_PU) + b * KINT + j] = ps[j];
}

// ---------------- PG(top) = local_proj_w[0:128] @ gcn_w ----------------------
__global__ void __launch_bounds__(128) pg_kernel(const float* __restrict__ P,
                                                 const float* __restrict__ G) {
    __shared__ float prow[DIM];
    int m = blockIdx.x;          // 0..127 (only top rows used by xw_gemm)
    int j = threadIdx.x;
    prow[j] = P[m * DIM + j];
    __syncthreads();
    float a = 0.f;
#pragma unroll 8
    for (int k = 0; k < DIM; k++) a += prow[k] * G[k * DIM + j];
    g_PG[m * DIM + j] = a;
}

// ---------------- D4[d] = (Pb + dist_emb[d] @ P_bot) @ G  (standalone) --------
__global__ void __launch_bounds__(128) d4_kernel(const float* __restrict__ dist_emb,
                                                 const float* __restrict__ P,
                                                 const float* __restrict__ Pb,
                                                 const float* __restrict__ G) {
    __shared__ float de[DIM];
    __shared__ float A[DIM];
    int d = blockIdx.x;          // 0..3
    int j = threadIdx.x;
    de[j] = dist_emb[d * DIM + j];
    __syncthreads();
    float ak = Pb[j];
#pragma unroll 8
    for (int m = 0; m < DIM; m++) ak += de[m] * P[(128 + m) * DIM + j];
    A[j] = ak;
    __syncthreads();
    float a = 0.f;
#pragma unroll 8
    for (int k = 0; k < DIM; k++) a += A[k] * G[k * DIM + j];
    g_D4[d * DIM + j] = a;
}

// ---------------- xw = repr(x_idx) @ PG_top + D4[dist_label]  (tf32 TC) ------
__global__ void __launch_bounds__(256) xw_gemm_tc(const int* __restrict__ x_idx,
                                                  const int* __restrict__ dist_label,
                                                  const float* __restrict__ ue,
                                                  const float* __restrict__ ie) {
    extern __shared__ float sm[];
    float* Wsm = sm;
    float* Xsm = sm + 128 * XS;
    int tid = threadIdx.x;
    int r0 = blockIdx.x * 128;

#pragma unroll
    for (int t = 0; t < 16; t++) {
        int i = tid + t * 256;
        int row = i >> 5, q = i & 31;
        float4 v = ((const float4*)g_PG)[row * 32 + q];
        *(float4*)&Wsm[row * XS + q * 4] = v;
    }
#pragma unroll
    for (int t = 0; t < 16; t++) {
        int i = tid + t * 256;
        int row = i >> 5, q = i & 31;
        int r = r0 + row;
        int node = x_idx[r];
        const float* p = (node < N_USERS) ? (ue + (size_t)node * DIM)
                                          : (ie + (size_t)(node - N_USERS) * DIM);
        float4 e4 = ((const float4*)p)[q];
        float4 a4 = ((const float4*)g_aggr)[(size_t)node * 32 + q];
        float4 v = make_float4(e4.x + fmaxf(a4.x, 0.f), e4.y + fmaxf(a4.y, 0.f),
                               e4.z + fmaxf(a4.z, 0.f), e4.w + fmaxf(a4.w, 0.f));
        *(float4*)&Xsm[row * XS + q * 4] = v;
    }
    __syncthreads();

    int warp = tid >> 5, lane = tid & 31;
    int gid = lane >> 2, tig = lane & 3;
    int wr = warp * 16;

    float acc[16][4];
#pragma unroll
    for (int n = 0; n < 16; n++)
#pragma unroll
        for (int m = 0; m < 4; m++) acc[n][m] = 0.f;

#pragma unroll
    for (int k = 0; k < 128; k += 8) {
        unsigned a0 = f2tf32(Xsm[(wr + gid) * XS + k + tig]);
        unsigned a1 = f2tf32(Xsm[(wr + gid + 8) * XS + k + tig]);
        unsigned a2 = f2tf32(Xsm[(wr + gid) * XS + k + tig + 4]);
        unsigned a3 = f2tf32(Xsm[(wr + gid + 8) * XS + k + tig + 4]);
#pragma unroll
        for (int n = 0; n < 16; n++) {
            unsigned b0 = f2tf32(Wsm[(k + tig) * XS + n * 8 + gid]);
            unsigned b1 = f2tf32(Wsm[(k + tig + 4) * XS + n * 8 + gid]);
            mma_tf32(acc[n], a0, a1, a2, a3, b0, b1);
        }
    }

    int row0 = r0 + wr + gid;
    int row1 = row0 + 8;
    int dl0 = dist_label[row0];
    int dl1 = dist_label[row1];
#pragma unroll
    for (int n = 0; n < 16; n++) {
        int c0 = n * 8 + tig * 2;
        float2 dv0 = *(const float2*)&g_D4[dl0 * DIM + c0];
        float2 dv1 = *(const float2*)&g_D4[dl1 * DIM + c0];
        float2 o0 = make_float2(acc[n][0] + dv0.x, acc[n][1] + dv0.y);
        float2 o1 = make_float2(acc[n][2] + dv1.x, acc[n][3] + dv1.y);
        *(float2*)&g_xw[(size_t)row0 * DIM + c0] = o0;
        *(float2*)&g_xw[(size_t)row1 * DIM + c0] = o1;
    }
}

// ---------------- local GCN gather; self-cleans lcnt/lcur ---------------------
__global__ void __launch_bounds__(256) lgather_kernel() {
    int warp = (blockIdx.x * blockDim.x + threadIdx.x) >> 5;
    int lane = threadIdx.x & 31;
    if (warp >= NL) return;
    int p   = g_lcnt[warp];
    int end = g_lcur[warp];
    if (lane == 0) { g_lcnt[warp] = 0; g_lcur[warp] = 0; }
    float dd = g_dinv[warp];
    float4 sv = ((const float4*)g_xw)[(size_t)warp * 32 + lane];
    float4 acc = make_float4(dd * sv.x, dd * sv.y, dd * sv.z, dd * sv.w);  // self loop
    for (; p + 1 < end; p += 2) {
        int s0 = ldcs_i(&g_lpack[p]);
        int s1 = ldcs_i(&g_lpack[p + 1]);
        float4 v0 = ((const float4*)g_xw)[(size_t)s0 * 32 + lane];
        float4 v1 = ((const float4*)g_xw)[(size_t)s1 * 32 + lane];
        float n0 = g_dinv[s0];
        float n1 = g_dinv[s1];
        acc.x += n0 * v0.x + n1 * v1.x;
        acc.y += n0 * v0.y + n1 * v1.y;
        acc.z += n0 * v0.z + n1 * v1.z;
        acc.w += n0 * v0.w + n1 * v1.w;
    }
    if (p < end) {
        int s = ldcs_i(&g_lpack[p]);
        float4 v = ((const float4*)g_xw)[(size_t)s * 32 + lane];
        float n = g_dinv[s];
        acc.x += n * v.x; acc.y += n * v.y; acc.z += n * v.z; acc.w += n * v.w;
    }
    acc.x *= dd; acc.y *= dd; acc.z *= dd; acc.w *= dd;
    ((float4*)g_lout)[(size_t)warp * 32 + lane] = acc;
}

// ---------------- pool + final MLP fused (same block index b) -----------------
__device__ int lower_bound_i(const int* a, int n, int v) {
    int lo = 0, hi = n;
    while (lo < hi) { int m = (lo + hi) >> 1; if (a[m] < v) lo = m + 1; else hi = m; }
    return lo;
}
__global__ void __launch_bounds__(128) pool_final_kernel(const int* __restrict__ batch,
                                                         const float* __restrict__ gcn_b,
                                                         const float* __restrict__ pool_w,
                                                         const float* __restrict__ pool_b,
                                                         const float* __restrict__ w1,
                                                         const float* __restrict__ b1,
                                                         const float* __restrict__ w2,
                                                         const float* __restrict__ b2,
                                                         float* __restrict__ out, int out_size) {
    __shared__ int seg[2];
    __shared__ float mean[DIM];
    __shared__ float v[4 * DIM];
    __shared__ float hid[64];
    int b = blockIdx.x;
    int j = threadIdx.x;
    if (j == 0) seg[0] = lower_bound_i(batch, NL, b);
    if (j == 1) seg[1] = lower_bound_i(batch, NL, b + 1);
    __syncthreads();
    int lo = seg[0], hi = seg[1];
    float acc = 0.f;
    for (int i = lo; i < hi; i++)
        acc += g_lout[(size_t)i * DIM + j];
    int cnt = hi - lo;
    mean[j] = (cnt > 0) ? (acc / (float)cnt + gcn_b[j]) : 0.f;
    __syncthreads();
    float t = pool_b[j];
#pragma unroll 8
    for (int k = 0; k < DIM; k++) t += mean[k] * pool_w[k * DIM + j];
    float h = tanhf(t);
    if (out_size >= OUT_TOTAL) out[OUT_HSUB + b * DIM + j] = h;

    v[j]           = h;
    v[DIM + j]     = g_gu[b * DIM + j];
    v[2 * DIM + j] = g_gi[b * DIM + j];
    v[3 * DIM + j] = g_ru[b * DIM + j] * g_rv[b * DIM + j];
    __syncthreads();
    if (j < 64) {
        float a = b1[j];
#pragma unroll 8
        for (int k = 0; k < 4 * DIM; k++) a += v[k] * w1[k * 64 + j];
        hid[j] = fmaxf(a, 0.f) * w2[j];
    }
    __syncthreads();
    if (j == 0) {
        float s = b2[0];
        for (int tte = 0; tte < 64; tte++) s += hid[tte];
        out[OUT_PRED + b] = 1.f / (1.f + expf(-s));
    }
}

// ---------------- launch ------------------------------------------------------
extern "C" void kernel_launch(void* const* d_in, const int* in_sizes, int n_in,
                              void* d_out, int out_size) {
    const int*   gei    = (const int*)d_in[0];
    const int*   gea    = (const int*)d_in[1];
    const int*   root_u = (const int*)d_in[2];
    const int*   root_i = (const int*)d_in[3];
    const int*   x_idx  = (const int*)d_in[4];
    const int*   dist_l = (const int*)d_in[5];
    const int*   lei    = (const int*)d_in[6];
    const int*   batch  = (const int*)d_in[7];
    const float* ue     = (const float*)d_in[8];
    const float* ie     = (const float*)d_in[9];
    const float* dist_e = (const float*)d_in[10];
    const float* c_u    = (const float*)d_in[11];
    const float* c_v    = (const float*)d_in[12];
    const float* gnn_W  = (const float*)d_in[13];
    const float* gnn_b  = (const float*)d_in[14];
    const float* sign_e = (const float*)d_in[15];
    const float* iw1    = (const float*)d_in[16];
    const float* ib1    = (const float*)d_in[17];
    const float* iw2    = (const float*)d_in[18];
    const float* ib2    = (const float*)d_in[19];
    const float* lpw    = (const float*)d_in[20];
    const float* lpb    = (const float*)d_in[21];
    const float* gcw    = (const float*)d_in[22];
    const float* gcb    = (const float*)d_in[23];
    const float* pow_   = (const float*)d_in[24];
    const float* pob    = (const float*)d_in[25];
    const float* fw1    = (const float*)d_in[26];
    const float* fb1    = (const float*)d_in[27];
    const float* fw2    = (const float*)d_in[28];
    const float* fb2    = (const float*)d_in[29];
    float* out = (float*)d_out;

    // Created once on the (uncaptured) correctness call; kept alive for capture.
    static cudaStream_t sA = nullptr;
    static cudaEvent_t evStart, evA;
    if (sA == nullptr) {
        cudaStreamCreateWithFlags(&sA, cudaStreamNonBlocking);
        cudaEventCreateWithFlags(&evStart, cudaEventDisableTiming);
        cudaEventCreateWithFlags(&evA,     cudaEventDisableTiming);
        cudaFuncSetAttribute(y_gemm_tc,  cudaFuncAttributeMaxDynamicSharedMemorySize, GEMM_SMEM);
        cudaFuncSetAttribute(xw_gemm_tc, cudaFuncAttributeMaxDynamicSharedMemorySize, GEMM_SMEM);
    }

    cudaEventRecord(evStart, 0);

    // stream A (fork): y_gemm + PG + D4 — independent of the CSR build
    cudaStreamWaitEvent(sA, evStart, 0);
    y_gemm_tc<<<(N_NODES + 127) / 128, 256, GEMM_SMEM, sA>>>(ue, ie, gnn_W, gnn_b);
    pg_kernel<<<128, 128, 0, sA>>>(lpw, gcw);
    d4_kernel<<<4, 128, 0, sA>>>(dist_e, lpw, lpb, gcw);
    cudaEventRecord(evA, sA);

    // main stream: CSR build (global + local merged); no init needed
    hist_both<<<(E_G + EL + 255) / 256, 256>>>(gei + E_G, lei + EL);
    scan_a_both<<<NSEG_G + NSEG_L, SCAN_B>>>();
    scan_c_both<<<NSEG_G + NSEG_L, SCAN_B>>>();
    fill_both<<<(E_G + EL + 255) / 256, 256>>>(gei, gei + E_G, gea, lei, lei + EL);

    // join: gather needs CSR (main) + Y (stream A); xw later needs PG/D4 (also evA)
    cudaStreamWaitEvent(0, evA, 0);
    gather_aggr<<<(N_NODES * 32 + 255) / 256, 256>>>(sign_e);

    intent_kernel<<<2 * BATCH, 128>>>(root_u, root_i, ue, ie,
                                      iw1, ib1, iw2, ib2, c_u, c_v, out, out_size);

    xw_gemm_tc<<<NL / 128, 256, GEMM_SMEM>>>(x_idx, dist_l, ue, ie);

    lgather_kernel<<<(NL * 32) / 256, 256>>>();
    pool_final_kernel<<<BATCH, 128>>>(batch, gcb, pow_, pob,
                                      fw1, fb1, fw2, fb2, out, out_size);
}